// round 4
// baseline (speedup 1.0000x reference)
#include <cuda_runtime.h>
#include <math.h>

#define BB 32
#define TT 512
#define TT1 513
#define SD 256
#define HD 512
#define BT (BB*TT)
#define MS (BT*SD)
#define MT (BT*TT)

__device__ __align__(128) float g_st[MS], g_se[MS], g_tp[MS], g_tc[MS], g_gg[MS];
__device__ __align__(128) float g_A[MT], g_L[MT], g_Li[MT], g_cat[MT], g_cat2[MT];
__device__ __align__(128) float g_cs[BT], g_ar[BT], g_dg[BT];
__device__ __align__(128) int   g_piv[BT];

// ---------------- elementwise ----------------
__global__ void split_k(const float* __restrict__ x) {
  int idx = blockIdx.x*blockDim.x + threadIdx.x;
  int c = idx & 511; int bt = idx >> 9;
  const float* xp = x + (size_t)bt*HD;
  if (c < SD) g_se[(size_t)bt*SD + c] = xp[c + ((c >= 128) ? 128 : 0)];
  else { int cc = c - SD; g_st[(size_t)bt*SD + cc] = xp[cc + 128 + ((cc >= 128) ? 128 : 0)]; }
}

__global__ void root_k(const float* __restrict__ wr, const int* __restrict__ seq) {
  int g = blockIdx.x*blockDim.x + threadIdx.x;
  int w = g >> 5, lane = g & 31;
  if (w >= BT) return;
  const float* s = g_st + (size_t)w*SD;
  float acc = 0.f;
  for (int c = lane; c < SD; c += 32) acc += s[c]*wr[c];
  for (int o = 16; o > 0; o >>= 1) acc += __shfl_down_sync(0xffffffffu, acc, o);
  if (lane == 0) {
    int b = w >> 9, t = w & 511;
    g_ar[w] = (t < seq[b]) ? expf(acc) : 0.0f;
  }
}

__global__ void buildA_k(const int* __restrict__ seq) {
  int idx = blockIdx.x*blockDim.x + threadIdx.x;
  int j = idx & 511, i = (idx >> 9) & 511, b = idx >> 18;
  int len = seq[b];
  float f = g_A[idx];
  g_A[idx] = (i != j && i < len && j < len) ? expf(f) : 0.0f;
}

__global__ void colsum_k() {
  int b = blockIdx.x, j = threadIdx.x;
  const float* a = g_A + (size_t)b*TT*TT;
  float s = 0.f;
  for (int i = 0; i < TT; ++i) s += a[(size_t)i*TT + j];
  g_cs[b*TT + j] = s;
}

__global__ void buildL_k(const int* __restrict__ seq) {
  int idx = blockIdx.x*blockDim.x + threadIdx.x;
  int j = idx & 511, i = (idx >> 9) & 511, b = idx >> 18;
  float v;
  if (i == 0) v = g_ar[b*TT + j];
  else {
    v = -g_A[idx];
    if (i == j) v += g_cs[b*TT + j] + ((j >= seq[b]) ? 1.0f : 0.0f);
  }
  g_L[idx] = v;
}

// ---------------- Gauss-Jordan inverse, partial pivoting (NR gaussj) ----------------
__global__ __launch_bounds__(1024) void invert_k() {
  int b = blockIdx.x;
  float* a = g_L + (size_t)b*TT*TT;
  __shared__ __align__(16) float rowk[TT];
  __shared__ float colk[TT];
  __shared__ float redv[16]; __shared__ int redi[16];
  __shared__ float sPinv; __shared__ int sIr;
  int tid = threadIdx.x;
  for (int k = 0; k < TT; ++k) {
    if (tid < TT) {
      float v = (tid >= k) ? fabsf(a[(size_t)tid*TT + k]) : -1.0f;
      int ix = tid;
      for (int o = 16; o > 0; o >>= 1) {
        float v2 = __shfl_down_sync(0xffffffffu, v, o);
        int   i2 = __shfl_down_sync(0xffffffffu, ix, o);
        if (v2 > v) { v = v2; ix = i2; }
      }
      if ((tid & 31) == 0) { redv[tid >> 5] = v; redi[tid >> 5] = ix; }
    }
    __syncthreads();
    if (tid == 0) {
      float v = redv[0]; int ix = redi[0];
      for (int w = 1; w < 16; ++w) if (redv[w] > v) { v = redv[w]; ix = redi[w]; }
      sIr = ix; g_piv[b*TT + k] = ix;
    }
    __syncthreads();
    int ir = sIr;
    if (ir != k && tid < 128) {
      float4* rk = (float4*)(a + (size_t)k*TT);
      float4* rr = (float4*)(a + (size_t)ir*TT);
      float4 t0 = rk[tid]; rk[tid] = rr[tid]; rr[tid] = t0;
    }
    __syncthreads();
    if (tid == 0) sPinv = 1.0f / a[(size_t)k*TT + k];
    __syncthreads();
    float pinv = sPinv;
    if (tid < 128) {
      float4 v = ((float4*)(a + (size_t)k*TT))[tid];
      if (tid == (k >> 2)) ((float*)&v)[k & 3] = 1.0f;
      v.x *= pinv; v.y *= pinv; v.z *= pinv; v.w *= pinv;
      ((float4*)rowk)[tid] = v;
      ((float4*)(a + (size_t)k*TT))[tid] = v;
    } else if (tid >= 512) {
      int i = tid - 512;
      colk[i] = a[(size_t)i*TT + k];
    }
    __syncthreads();
    int jt = tid & 127, it = tid >> 7;
    float4 rk4 = ((float4*)rowk)[jt];
    int kj = k >> 2, kc = k & 3;
    for (int i = it; i < TT; i += 8) {
      if (i == k) continue;
      float c = colk[i];
      float4* pp = (float4*)(a + (size_t)i*TT) + jt;
      float4 v = *pp;
      if (jt == kj) ((float*)&v)[kc] = 0.0f;
      v.x -= c*rk4.x; v.y -= c*rk4.y; v.z -= c*rk4.z; v.w -= c*rk4.w;
      *pp = v;
    }
    __syncthreads();
  }
}

__global__ __launch_bounds__(1024) void gather_k() {
  __shared__ int arr[TT];
  int b = blockIdx.x, tid = threadIdx.x;
  if (tid == 0) {
    for (int j = 0; j < TT; ++j) arr[j] = j;
    for (int l = TT-1; l >= 0; --l) {
      int p = g_piv[b*TT + l];
      if (p != l) { int t = arr[l]; arr[l] = arr[p]; arr[p] = t; }
    }
  }
  __syncthreads();
  const float* a = g_L + (size_t)b*TT*TT;
  float* o = g_Li + (size_t)b*TT*TT;
  for (int idx = tid; idx < TT*TT; idx += 1024) {
    int i = idx >> 9, j = idx & 511;
    o[idx] = a[(size_t)i*TT + arr[j]];
  }
}

__global__ void diag_k(float* __restrict__ out2) {
  int b = blockIdx.x, j = threadIdx.x;
  const float* L = g_Li + (size_t)b*TT*TT;
  g_dg[b*TT + j] = L[(size_t)j*TT + j];
  out2[(size_t)b*TT1*TT + j] = g_ar[b*TT + j] * L[(size_t)j*TT];
}

__global__ __launch_bounds__(1024) void pij_k(float* __restrict__ out2) {
  __shared__ float Ts[32][33];
  int b = blockIdx.z;
  int i0 = blockIdx.y*32, j0 = blockIdx.x*32;
  int tx = threadIdx.x, ty = threadIdx.y;
  const float* L = g_Li + (size_t)b*TT*TT;
  Ts[ty][tx] = L[(size_t)(j0+ty)*TT + i0 + tx];
  __syncthreads();
  int i = i0 + ty, j = j0 + tx;
  float av  = g_A[(size_t)b*TT*TT + (size_t)i*TT + j];
  float dj  = (j > 0) ? g_dg[b*TT + j] : 0.0f;
  float lji = (i > 0) ? Ts[tx][ty] : 0.0f;
  out2[(size_t)b*TT1*TT + (size_t)(i+1)*TT + j] = av * (dj - lji);
}

__global__ void addroot_k(const float* __restrict__ re, const float* __restrict__ out2) {
  int idx = blockIdx.x*blockDim.x + threadIdx.x;
  int c = idx & 255, bi = idx >> 8;
  int b = bi >> 9, i = bi & 511;
  float pr = out2[(size_t)b*TT1*TT + i];
  g_cat[(size_t)bi*HD + c] += pr * re[c];
}

// ---------------- generic tiled GEMM ----------------
// MODE 0: C = A(MxK) * B(NxK)^T ; MODE 1: C = A(MxK) * B(KxN) ; MODE 2: C = A(KxM)^T * B(KxN)
#define BKD 16
#define PADW 68
template<int MODE>
__global__ __launch_bounds__(256)
void gemm_k(const float* __restrict__ A, int lda, long long sA,
            const float* __restrict__ B, int ldb, long long sB,
            float* __restrict__ C, int ldc, long long sC,
            int K, const float* __restrict__ bias, int act)
{
  __shared__ __align__(16) float As[BKD*PADW];
  __shared__ __align__(16) float Bs[BKD*PADW];
  const int tid = threadIdx.x;
  const int tx = tid & 15, ty = tid >> 4;
  const int m0 = blockIdx.y*64, n0 = blockIdx.x*64;
  const float* Ab = A + (size_t)blockIdx.z*sA;
  const float* Bb = B + (size_t)blockIdx.z*sB;
  float* Cb = C + (size_t)blockIdx.z*sC;
  const int r4 = tid >> 2, k4 = (tid & 3)*4;
  const int k16 = tid >> 4, c16 = (tid & 15)*4;
  float acc[4][4] = {};
  for (int k0 = 0; k0 < K; k0 += BKD) {
    float4 aL, bL;
    if (MODE == 2) aL = *(const float4*)(Ab + (size_t)(k0+k16)*lda + m0 + c16);
    else           aL = *(const float4*)(Ab + (size_t)(m0+r4)*lda + k0 + k4);
    if (MODE == 0) bL = *(const float4*)(Bb + (size_t)(n0+r4)*ldb + k0 + k4);
    else           bL = *(const float4*)(Bb + (size_t)(k0+k16)*ldb + n0 + c16);
    __syncthreads();
    if (MODE == 2) *(float4*)(As + k16*PADW + c16) = aL;
    else {
      As[(k4+0)*PADW + r4] = aL.x; As[(k4+1)*PADW + r4] = aL.y;
      As[(k4+2)*PADW + r4] = aL.z; As[(k4+3)*PADW + r4] = aL.w;
    }
    if (MODE == 0) {
      Bs[(k4+0)*PADW + r4] = bL.x; Bs[(k4+1)*PADW + r4] = bL.y;
      Bs[(k4+2)*PADW + r4] = bL.z; Bs[(k4+3)*PADW + r4] = bL.w;
    } else *(float4*)(Bs + k16*PADW + c16) = bL;
    __syncthreads();
#pragma unroll
    for (int kk = 0; kk < BKD; ++kk) {
      float4 av = *(const float4*)(As + kk*PADW + ty*4);
      float4 bv = *(const float4*)(Bs + kk*PADW + tx*4);
      acc[0][0] += av.x*bv.x; acc[0][1] += av.x*bv.y; acc[0][2] += av.x*bv.z; acc[0][3] += av.x*bv.w;
      acc[1][0] += av.y*bv.x; acc[1][1] += av.y*bv.y; acc[1][2] += av.y*bv.z; acc[1][3] += av.y*bv.w;
      acc[2][0] += av.z*bv.x; acc[2][1] += av.z*bv.y; acc[2][2] += av.z*bv.z; acc[2][3] += av.z*bv.w;
      acc[3][0] += av.w*bv.x; acc[3][1] += av.w*bv.y; acc[3][2] += av.w*bv.z; acc[3][3] += av.w*bv.w;
    }
  }
  float4 bb = make_float4(0.f,0.f,0.f,0.f);
  if (bias) { const float* bp = bias + n0 + tx*4; bb = make_float4(bp[0],bp[1],bp[2],bp[3]); }
#pragma unroll
  for (int i = 0; i < 4; ++i) {
    float4 v = make_float4(acc[i][0]+bb.x, acc[i][1]+bb.y, acc[i][2]+bb.z, acc[i][3]+bb.w);
    if (act == 1) { v.x=tanhf(v.x); v.y=tanhf(v.y); v.z=tanhf(v.z); v.w=tanhf(v.w); }
    else if (act == 2) {
      v.x = v.x>=0.f?v.x:0.01f*v.x; v.y = v.y>=0.f?v.y:0.01f*v.y;
      v.z = v.z>=0.f?v.z:0.01f*v.z; v.w = v.w>=0.f?v.w:0.01f*v.w;
    }
    *(float4*)(Cb + (size_t)(m0+ty*4+i)*ldc + n0 + tx*4) = v;
  }
}

// ---------------- launch ----------------
extern "C" void kernel_launch(void* const* d_in, const int* in_sizes, int n_in,
                              void* d_out, int out_size) {
  (void)in_sizes; (void)n_in; (void)out_size;
  const float* x     = (const float*)d_in[0];
  const int*   seq   = (const int*)  d_in[1];
  const float* W_tp  = (const float*)d_in[2];
  const float* b_tp  = (const float*)d_in[3];
  const float* W_tc  = (const float*)d_in[4];
  const float* b_tc  = (const float*)d_in[5];
  const float* W_fij = (const float*)d_in[6];
  const float* w_root= (const float*)d_in[7];
  const float* r_emb = (const float*)d_in[8];
  const float* W_r   = (const float*)d_in[9];
  const float* b_r   = (const float*)d_in[10];
  const float* W_pc  = (const float*)d_in[11];
  const float* b_pc  = (const float*)d_in[12];
  float* out1 = (float*)d_out;
  float* out2 = out1 + (size_t)BT*SD;

  float *st,*se,*tp,*tc,*gg,*A,*cat,*cat2;
  cudaGetSymbolAddress((void**)&st,   g_st);
  cudaGetSymbolAddress((void**)&se,   g_se);
  cudaGetSymbolAddress((void**)&tp,   g_tp);
  cudaGetSymbolAddress((void**)&tc,   g_tc);
  cudaGetSymbolAddress((void**)&gg,   g_gg);
  cudaGetSymbolAddress((void**)&A,    g_A);
  cudaGetSymbolAddress((void**)&cat,  g_cat);
  cudaGetSymbolAddress((void**)&cat2, g_cat2);

  const long long sTT = (long long)TT*TT, sTS = (long long)TT*SD,
                  sTH = (long long)TT*HD, sP = (long long)TT1*TT;
  const float* pij = out2 + TT;   // rows 1..512 of each (513,512) batch slab

  split_k<<<BT*HD/256, 256>>>(x);
  gemm_k<0><<<dim3(4,256,1),256>>>(st, SD, 0, W_tp, SD, 0, tp, SD, 0, SD, b_tp, 1);
  gemm_k<0><<<dim3(4,256,1),256>>>(st, SD, 0, W_tc, SD, 0, tc, SD, 0, SD, b_tc, 1);
  gemm_k<1><<<dim3(4,256,1),256>>>(tp, SD, 0, W_fij, SD, 0, gg, SD, 0, SD, 0, 0);
  gemm_k<0><<<dim3(8,8,BB),256>>>(gg, SD, sTS, tc, SD, sTS, A, TT, sTT, SD, 0, 0);
  root_k<<<BT*32/256, 256>>>(w_root, seq);
  buildA_k<<<MT/256, 256>>>(seq);
  colsum_k<<<BB, TT>>>();
  buildL_k<<<MT/256, 256>>>(seq);
  invert_k<<<BB, 1024>>>();
  gather_k<<<BB, 1024>>>();
  diag_k<<<BB, TT>>>(out2);
  pij_k<<<dim3(16,16,BB), dim3(32,32)>>>(out2);
  gemm_k<2><<<dim3(4,8,BB),256>>>(pij, TT, sP, se, SD, sTS, cat, HD, sTH, TT, 0, 0);
  addroot_k<<<MS/256, 256>>>(r_emb, out2);
  gemm_k<1><<<dim3(4,8,BB),256>>>(pij, TT, sP, se, SD, sTS, cat + SD, HD, sTH, TT, 0, 0);
  gemm_k<0><<<dim3(4,256,1),256>>>(cat, HD, 0, W_r, HD, 0, cat2, HD, 0, HD, b_r, 2);
  gemm_k<1><<<dim3(4,8,BB),256>>>(pij, TT, sP, cat2, HD, sTH, cat2 + SD, HD, sTH, TT, 0, 0);
  gemm_k<0><<<dim3(4,256,1),256>>>(cat2, HD, 0, W_pc, HD, 0, out1, SD, 0, HD, b_pc, 2);
}

// round 5
// speedup vs baseline: 4.5199x; 4.5199x over previous
#include <cuda_runtime.h>
#include <math.h>

#define BB 32
#define TT 512
#define TT1 513
#define SD 256
#define HD 512
#define BT (BB*TT)
#define MS (BT*SD)
#define MT (BT*TT)
#define NB 32

__device__ __align__(128) float g_st[MS], g_se[MS], g_tp[MS], g_tc[MS], g_gg[MS];
__device__ __align__(128) float g_A[MT], g_L[MT], g_Li[MT], g_cat[MT], g_cat2[MT];
__device__ __align__(128) float g_cs[BT], g_ar[BT], g_dg[BT];
__device__ __align__(128) int   g_piv[BT];

// ---------------- elementwise ----------------
__global__ void split_k(const float* __restrict__ x) {
  int idx = blockIdx.x*blockDim.x + threadIdx.x;
  int c = idx & 511; int bt = idx >> 9;
  const float* xp = x + (size_t)bt*HD;
  if (c < SD) g_se[(size_t)bt*SD + c] = xp[c + ((c >= 128) ? 128 : 0)];
  else { int cc = c - SD; g_st[(size_t)bt*SD + cc] = xp[cc + 128 + ((cc >= 128) ? 128 : 0)]; }
}

__global__ void root_k(const float* __restrict__ wr, const int* __restrict__ seq) {
  int g = blockIdx.x*blockDim.x + threadIdx.x;
  int w = g >> 5, lane = g & 31;
  if (w >= BT) return;
  const float* s = g_st + (size_t)w*SD;
  float acc = 0.f;
  for (int c = lane; c < SD; c += 32) acc += s[c]*wr[c];
  for (int o = 16; o > 0; o >>= 1) acc += __shfl_down_sync(0xffffffffu, acc, o);
  if (lane == 0) {
    int b = w >> 9, t = w & 511;
    g_ar[w] = (t < seq[b]) ? expf(acc) : 0.0f;
  }
}

__global__ void buildA_k(const int* __restrict__ seq) {
  int idx = blockIdx.x*blockDim.x + threadIdx.x;
  int j = idx & 511, i = (idx >> 9) & 511, b = idx >> 18;
  int len = seq[b];
  float f = g_A[idx];
  g_A[idx] = (i != j && i < len && j < len) ? expf(f) : 0.0f;
}

__global__ void colsum_k() {
  int b = blockIdx.x, j = threadIdx.x;
  const float* a = g_A + (size_t)b*TT*TT;
  float s = 0.f;
  for (int i = 0; i < TT; ++i) s += a[(size_t)i*TT + j];
  g_cs[b*TT + j] = s;
}

__global__ void buildL_k(const int* __restrict__ seq) {
  int idx = blockIdx.x*blockDim.x + threadIdx.x;
  int j = idx & 511, i = (idx >> 9) & 511, b = idx >> 18;
  float v;
  if (i == 0) v = g_ar[b*TT + j];
  else {
    v = -g_A[idx];
    if (i == j) v += g_cs[b*TT + j] + ((j >= seq[b]) ? 1.0f : 0.0f);
  }
  g_L[idx] = v;
}

// ---------------- blocked Gauss-Jordan inverse (NB=32, partial pivoting) ----------------
// panel_k: factor 512x32 panel in smem with the exact unblocked pivot sequence,
// apply row swaps to gmem, write the finalized panel back.
__global__ __launch_bounds__(1024) void panel_k(int k0) {
  extern __shared__ float panel[];  // 512 x 33
  __shared__ float colM[TT];
  __shared__ float redv[32]; __shared__ int redi[32];
  __shared__ float sPinv; __shared__ int sIr;
  __shared__ int spiv[NB];
  int b = blockIdx.x, tid = threadIdx.x;
  float* a = g_L + (size_t)b*TT*TT;
  for (int idx = tid; idx < TT*NB; idx += 1024) {
    int i = idx >> 5, c = idx & 31;
    panel[i*33+c] = a[(size_t)i*TT + k0 + c];
  }
  __syncthreads();
  for (int kk = 0; kk < NB; ++kk) {
    int k = k0 + kk;
    float v = -1.0f; int ix = tid;
    if (tid < TT && tid >= k) v = fabsf(panel[tid*33+kk]);
    for (int o = 16; o > 0; o >>= 1) {
      float v2 = __shfl_down_sync(0xffffffffu, v, o);
      int   i2 = __shfl_down_sync(0xffffffffu, ix, o);
      if (v2 > v) { v = v2; ix = i2; }
    }
    if ((tid & 31) == 0) { redv[tid>>5] = v; redi[tid>>5] = ix; }
    __syncthreads();
    if (tid == 0) {
      float bv = redv[0]; int bi = redi[0];
      for (int w = 1; w < 32; ++w) if (redv[w] > bv) { bv = redv[w]; bi = redi[w]; }
      sIr = bi; spiv[kk] = bi; g_piv[b*TT+k] = bi;
    }
    __syncthreads();
    int ir = sIr;
    if (ir != k && tid < NB) {
      float t = panel[k*33+tid]; panel[k*33+tid] = panel[ir*33+tid]; panel[ir*33+tid] = t;
    }
    __syncthreads();
    if (tid == 0) sPinv = 1.0f / panel[k*33+kk];
    __syncthreads();
    float pinv = sPinv;
    if (tid < NB) {
      float val = panel[k*33+tid];
      if (tid == kk) val = 1.0f;
      panel[k*33+tid] = val * pinv;
    } else if (tid >= 64 && tid < 64+TT) {
      colM[tid-64] = panel[(tid-64)*33+kk];   // colM[k] is unused
    }
    __syncthreads();
    for (int idx = tid; idx < TT*NB; idx += 1024) {
      int i = idx >> 5, c = idx & 31;
      if (i == k) continue;
      float m  = colM[i];
      float rk = panel[k*33+c];
      float cur = (c == kk) ? 0.0f : panel[i*33+c];
      panel[i*33+c] = cur - m*rk;
    }
    __syncthreads();
  }
  // apply the 32 recorded row swaps to the full gmem matrix (sequentially)
  for (int s = 0; s < NB; ++s) {
    int k = k0 + s, ir = spiv[s];
    if (ir != k && tid < 128) {
      float4* rk = (float4*)(a + (size_t)k*TT);
      float4* rr = (float4*)(a + (size_t)ir*TT);
      float4 t = rk[tid]; rk[tid] = rr[tid]; rr[tid] = t;
    }
    __syncthreads();
  }
  // write finalized panel (block columns) back
  for (int idx = tid; idx < TT*NB; idx += 1024) {
    int i = idx >> 5, c = idx & 31;
    a[(size_t)i*TT + k0 + c] = panel[i*33+c];
  }
}

// update_k: C[i][j] = [i not in blk]*A[i][j] + P[i][:] . R[:][j] for j outside the block.
// grid (4 column-slices x 32 matrices), 128-col slice per CTA.
__global__ __launch_bounds__(1024) void update_k(int k0) {
  extern __shared__ float sm[];
  float* Ps = sm;           // 512 x 33
  float* Rs = sm + TT*33;   // 32 x 132
  int b = blockIdx.y, tid = threadIdx.x;
  int jbase = blockIdx.x * 128;
  float* a = g_L + (size_t)b*TT*TT;
  for (int idx = tid; idx < TT*NB; idx += 1024) {
    int i = idx >> 5, c = idx & 31;
    Ps[i*33+c] = a[(size_t)i*TT + k0 + c];
  }
  for (int idx = tid; idx < NB*128; idx += 1024) {
    int k = idx >> 7, c = idx & 127;
    Rs[k*132+c] = a[(size_t)(k0+k)*TT + jbase + c];
  }
  __syncthreads();
  int tx = tid & 31, ty = tid >> 5;
  int j = jbase + tx*4;
  if (j >= k0 && j < k0 + NB) return;   // block columns already final
  for (int r = 0; r < 4; ++r) {
    int i0 = r*128 + ty*4;
    float acc[4][4] = {};
#pragma unroll 8
    for (int k = 0; k < NB; ++k) {
      float4 rv = *(const float4*)(Rs + k*132 + tx*4);
      float p0 = Ps[(i0+0)*33+k], p1 = Ps[(i0+1)*33+k];
      float p2 = Ps[(i0+2)*33+k], p3 = Ps[(i0+3)*33+k];
      acc[0][0]+=p0*rv.x; acc[0][1]+=p0*rv.y; acc[0][2]+=p0*rv.z; acc[0][3]+=p0*rv.w;
      acc[1][0]+=p1*rv.x; acc[1][1]+=p1*rv.y; acc[1][2]+=p1*rv.z; acc[1][3]+=p1*rv.w;
      acc[2][0]+=p2*rv.x; acc[2][1]+=p2*rv.y; acc[2][2]+=p2*rv.z; acc[2][3]+=p2*rv.w;
      acc[3][0]+=p3*rv.x; acc[3][1]+=p3*rv.y; acc[3][2]+=p3*rv.z; acc[3][3]+=p3*rv.w;
    }
#pragma unroll
    for (int q = 0; q < 4; ++q) {
      int i = i0 + q;
      float4 res;
      if (i >= k0 && i < k0 + NB) res = make_float4(0.f,0.f,0.f,0.f);
      else res = *(const float4*)(a + (size_t)i*TT + j);
      res.x += acc[q][0]; res.y += acc[q][1]; res.z += acc[q][2]; res.w += acc[q][3];
      *(float4*)(a + (size_t)i*TT + j) = res;
    }
  }
}

__global__ __launch_bounds__(1024) void gather_k() {
  __shared__ int arr[TT];
  int b = blockIdx.x, tid = threadIdx.x;
  if (tid == 0) {
    for (int j = 0; j < TT; ++j) arr[j] = j;
    for (int l = TT-1; l >= 0; --l) {
      int p = g_piv[b*TT + l];
      if (p != l) { int t = arr[l]; arr[l] = arr[p]; arr[p] = t; }
    }
  }
  __syncthreads();
  const float* a = g_L + (size_t)b*TT*TT;
  float* o = g_Li + (size_t)b*TT*TT;
  for (int idx = tid; idx < TT*TT; idx += 1024) {
    int i = idx >> 9, j = idx & 511;
    o[idx] = a[(size_t)i*TT + arr[j]];
  }
}

__global__ void diag_k(float* __restrict__ out2) {
  int b = blockIdx.x, j = threadIdx.x;
  const float* L = g_Li + (size_t)b*TT*TT;
  g_dg[b*TT + j] = L[(size_t)j*TT + j];
  out2[(size_t)b*TT1*TT + j] = g_ar[b*TT + j] * L[(size_t)j*TT];
}

__global__ __launch_bounds__(1024) void pij_k(float* __restrict__ out2) {
  __shared__ float Ts[32][33];
  int b = blockIdx.z;
  int i0 = blockIdx.y*32, j0 = blockIdx.x*32;
  int tx = threadIdx.x, ty = threadIdx.y;
  const float* L = g_Li + (size_t)b*TT*TT;
  Ts[ty][tx] = L[(size_t)(j0+ty)*TT + i0 + tx];
  __syncthreads();
  int i = i0 + ty, j = j0 + tx;
  float av  = g_A[(size_t)b*TT*TT + (size_t)i*TT + j];
  float dj  = (j > 0) ? g_dg[b*TT + j] : 0.0f;
  float lji = (i > 0) ? Ts[tx][ty] : 0.0f;
  out2[(size_t)b*TT1*TT + (size_t)(i+1)*TT + j] = av * (dj - lji);
}

__global__ void addroot_k(const float* __restrict__ re, const float* __restrict__ out2) {
  int idx = blockIdx.x*blockDim.x + threadIdx.x;
  int c = idx & 255, bi = idx >> 8;
  int b = bi >> 9, i = bi & 511;
  float pr = out2[(size_t)b*TT1*TT + i];
  g_cat[(size_t)bi*HD + c] += pr * re[c];
}

// ---------------- generic tiled GEMM ----------------
// MODE 0: C = A(MxK) * B(NxK)^T ; MODE 1: C = A(MxK) * B(KxN) ; MODE 2: C = A(KxM)^T * B(KxN)
#define BKD 16
#define PADW 68
template<int MODE>
__global__ __launch_bounds__(256)
void gemm_k(const float* __restrict__ A, int lda, long long sA,
            const float* __restrict__ B, int ldb, long long sB,
            float* __restrict__ C, int ldc, long long sC,
            int K, const float* __restrict__ bias, int act)
{
  __shared__ __align__(16) float As[BKD*PADW];
  __shared__ __align__(16) float Bs[BKD*PADW];
  const int tid = threadIdx.x;
  const int tx = tid & 15, ty = tid >> 4;
  const int m0 = blockIdx.y*64, n0 = blockIdx.x*64;
  const float* Ab = A + (size_t)blockIdx.z*sA;
  const float* Bb = B + (size_t)blockIdx.z*sB;
  float* Cb = C + (size_t)blockIdx.z*sC;
  const int r4 = tid >> 2, k4 = (tid & 3)*4;
  const int k16 = tid >> 4, c16 = (tid & 15)*4;
  float acc[4][4] = {};
  for (int k0 = 0; k0 < K; k0 += BKD) {
    float4 aL, bL;
    if (MODE == 2) aL = *(const float4*)(Ab + (size_t)(k0+k16)*lda + m0 + c16);
    else           aL = *(const float4*)(Ab + (size_t)(m0+r4)*lda + k0 + k4);
    if (MODE == 0) bL = *(const float4*)(Bb + (size_t)(n0+r4)*ldb + k0 + k4);
    else           bL = *(const float4*)(Bb + (size_t)(k0+k16)*ldb + n0 + c16);
    __syncthreads();
    if (MODE == 2) *(float4*)(As + k16*PADW + c16) = aL;
    else {
      As[(k4+0)*PADW + r4] = aL.x; As[(k4+1)*PADW + r4] = aL.y;
      As[(k4+2)*PADW + r4] = aL.z; As[(k4+3)*PADW + r4] = aL.w;
    }
    if (MODE == 0) {
      Bs[(k4+0)*PADW + r4] = bL.x; Bs[(k4+1)*PADW + r4] = bL.y;
      Bs[(k4+2)*PADW + r4] = bL.z; Bs[(k4+3)*PADW + r4] = bL.w;
    } else *(float4*)(Bs + k16*PADW + c16) = bL;
    __syncthreads();
#pragma unroll
    for (int kk = 0; kk < BKD; ++kk) {
      float4 av = *(const float4*)(As + kk*PADW + ty*4);
      float4 bv = *(const float4*)(Bs + kk*PADW + tx*4);
      acc[0][0] += av.x*bv.x; acc[0][1] += av.x*bv.y; acc[0][2] += av.x*bv.z; acc[0][3] += av.x*bv.w;
      acc[1][0] += av.y*bv.x; acc[1][1] += av.y*bv.y; acc[1][2] += av.y*bv.z; acc[1][3] += av.y*bv.w;
      acc[2][0] += av.z*bv.x; acc[2][1] += av.z*bv.y; acc[2][2] += av.z*bv.z; acc[2][3] += av.z*bv.w;
      acc[3][0] += av.w*bv.x; acc[3][1] += av.w*bv.y; acc[3][2] += av.w*bv.z; acc[3][3] += av.w*bv.w;
    }
  }
  float4 bb = make_float4(0.f,0.f,0.f,0.f);
  if (bias) { const float* bp = bias + n0 + tx*4; bb = make_float4(bp[0],bp[1],bp[2],bp[3]); }
#pragma unroll
  for (int i = 0; i < 4; ++i) {
    float4 v = make_float4(acc[i][0]+bb.x, acc[i][1]+bb.y, acc[i][2]+bb.z, acc[i][3]+bb.w);
    if (act == 1) { v.x=tanhf(v.x); v.y=tanhf(v.y); v.z=tanhf(v.z); v.w=tanhf(v.w); }
    else if (act == 2) {
      v.x = v.x>=0.f?v.x:0.01f*v.x; v.y = v.y>=0.f?v.y:0.01f*v.y;
      v.z = v.z>=0.f?v.z:0.01f*v.z; v.w = v.w>=0.f?v.w:0.01f*v.w;
    }
    *(float4*)(Cb + (size_t)(m0+ty*4+i)*ldc + n0 + tx*4) = v;
  }
}

// ---------------- launch ----------------
extern "C" void kernel_launch(void* const* d_in, const int* in_sizes, int n_in,
                              void* d_out, int out_size) {
  (void)in_sizes; (void)n_in; (void)out_size;
  const float* x     = (const float*)d_in[0];
  const int*   seq   = (const int*)  d_in[1];
  const float* W_tp  = (const float*)d_in[2];
  const float* b_tp  = (const float*)d_in[3];
  const float* W_tc  = (const float*)d_in[4];
  const float* b_tc  = (const float*)d_in[5];
  const float* W_fij = (const float*)d_in[6];
  const float* w_root= (const float*)d_in[7];
  const float* r_emb = (const float*)d_in[8];
  const float* W_r   = (const float*)d_in[9];
  const float* b_r   = (const float*)d_in[10];
  const float* W_pc  = (const float*)d_in[11];
  const float* b_pc  = (const float*)d_in[12];
  float* out1 = (float*)d_out;
  float* out2 = out1 + (size_t)BT*SD;

  float *st,*se,*tp,*tc,*gg,*A,*cat,*cat2;
  cudaGetSymbolAddress((void**)&st,   g_st);
  cudaGetSymbolAddress((void**)&se,   g_se);
  cudaGetSymbolAddress((void**)&tp,   g_tp);
  cudaGetSymbolAddress((void**)&tc,   g_tc);
  cudaGetSymbolAddress((void**)&gg,   g_gg);
  cudaGetSymbolAddress((void**)&A,    g_A);
  cudaGetSymbolAddress((void**)&cat,  g_cat);
  cudaGetSymbolAddress((void**)&cat2, g_cat2);

  const int PANEL_SMEM  = TT*33*4;              // 67584
  const int UPDATE_SMEM = TT*33*4 + NB*132*4;   // 84480
  cudaFuncSetAttribute(panel_k,  cudaFuncAttributeMaxDynamicSharedMemorySize, PANEL_SMEM);
  cudaFuncSetAttribute(update_k, cudaFuncAttributeMaxDynamicSharedMemorySize, UPDATE_SMEM);

  const long long sTT = (long long)TT*TT, sTS = (long long)TT*SD,
                  sTH = (long long)TT*HD, sP = (long long)TT1*TT;
  const float* pij = out2 + TT;   // rows 1..512 of each (513,512) batch slab

  split_k<<<BT*HD/256, 256>>>(x);
  gemm_k<0><<<dim3(4,256,1),256>>>(st, SD, 0, W_tp, SD, 0, tp, SD, 0, SD, b_tp, 1);
  gemm_k<0><<<dim3(4,256,1),256>>>(st, SD, 0, W_tc, SD, 0, tc, SD, 0, SD, b_tc, 1);
  gemm_k<1><<<dim3(4,256,1),256>>>(tp, SD, 0, W_fij, SD, 0, gg, SD, 0, SD, 0, 0);
  gemm_k<0><<<dim3(8,8,BB),256>>>(gg, SD, sTS, tc, SD, sTS, A, TT, sTT, SD, 0, 0);
  root_k<<<BT*32/256, 256>>>(w_root, seq);
  buildA_k<<<MT/256, 256>>>(seq);
  colsum_k<<<BB, TT>>>();
  buildL_k<<<MT/256, 256>>>(seq);
  for (int kb = 0; kb < TT/NB; ++kb) {
    panel_k<<<BB, 1024, PANEL_SMEM>>>(kb*NB);
    update_k<<<dim3(4, BB), 1024, UPDATE_SMEM>>>(kb*NB);
  }
  gather_k<<<BB, 1024>>>();
  diag_k<<<BB, TT>>>(out2);
  pij_k<<<dim3(16,16,BB), dim3(32,32)>>>(out2);
  gemm_k<2><<<dim3(4,8,BB),256>>>(pij, TT, sP, se, SD, sTS, cat, HD, sTH, TT, 0, 0);
  addroot_k<<<MS/256, 256>>>(r_emb, out2);
  gemm_k<1><<<dim3(4,8,BB),256>>>(pij, TT, sP, se, SD, sTS, cat + SD, HD, sTH, TT, 0, 0);
  gemm_k<0><<<dim3(4,256,1),256>>>(cat, HD, 0, W_r, HD, 0, cat2, HD, 0, HD, b_r, 2);
  gemm_k<1><<<dim3(4,8,BB),256>>>(pij, TT, sP, cat2, HD, sTH, cat2 + SD, HD, sTH, TT, 0, 0);
  gemm_k<0><<<dim3(4,256,1),256>>>(cat2, HD, 0, W_pc, HD, 0, out1, SD, 0, HD, b_pc, 2);
}